// round 1
// baseline (speedup 1.0000x reference)
#include <cuda_runtime.h>

// Fused sparse-UNet backbone: 13 chained per-row matmuls + relu/concat/pair-sum.
// One CTA processes RROWS rows; activations live in SMEM (channel-major,
// pitch = RROWS+1 to avoid bank conflicts); weights for the current stage are
// staged into a shared 64KB buffer (K-split for the 256x128 merge weight).
// Register tile TR x TC per thread keeps FMA:LDS at 2:1 so the kernel is
// FFMA-pipe bound, not smem-bound.

#define THREADS 256
#define RROWS   64
#define PITCH   (RROWS + 1)

__device__ __forceinline__ float frelu(float v) { return v > 0.f ? v : 0.f; }

// EPI: 0 = relu -> smem dst ; 1 = relu(acc)+pairsum(redSrc) -> smem dst ;
//      2 = relu -> global out [N, COUT] row-major
template<int CIN, int COUT, int TR, int TC, int EPI>
__device__ __forceinline__ void mm(const float* __restrict__ sSrc,
                                   const float* __restrict__ Wg,
                                   float* __restrict__ sW,
                                   float* __restrict__ dst,
                                   const float* __restrict__ redSrc,
                                   float* __restrict__ gout,
                                   int row0, int Ntot, int tid)
{
    constexpr int tiles_c = COUT / TC;
    constexpr int tiles_r = RROWS / TR;
    constexpr int ntiles  = tiles_c * tiles_r;
    constexpr int TPT     = ntiles / THREADS;          // 1 or 2, exact by construction
    constexpr int NCHUNK  = (CIN > 128) ? (CIN / 128) : 1;
    constexpr int KC      = CIN / NCHUNK;              // <= 128

    float acc[TPT][TR][TC];
#pragma unroll
    for (int t = 0; t < TPT; t++)
#pragma unroll
        for (int i = 0; i < TR; i++)
#pragma unroll
            for (int j = 0; j < TC; j++) acc[t][i][j] = 0.f;

    for (int ch = 0; ch < NCHUNK; ch++) {
        __syncthreads();                                // prev stage done / sW free
        {   // cooperative weight chunk load (float4)
            const float4* ws = (const float4*)(Wg + (size_t)ch * KC * COUT);
            float4* wd = (float4*)sW;
            constexpr int WN = KC * COUT / 4;
            for (int i = tid; i < WN; i += THREADS) wd[i] = ws[i];
        }
        __syncthreads();

#pragma unroll
        for (int t = 0; t < TPT; t++) {
            const int tile = tid + t * THREADS;
            const int tc = tile % tiles_c;
            const int tr = tile / tiles_c;
            const float* sp = sSrc + (size_t)ch * KC * PITCH + tr * TR;
            const float* wp = sW + tc;
#pragma unroll 4
            for (int k = 0; k < KC; k++) {
                float a[TR], w[TC];
#pragma unroll
                for (int i = 0; i < TR; i++) a[i] = sp[k * PITCH + i];
#pragma unroll
                for (int j = 0; j < TC; j++) w[j] = wp[k * COUT + j * tiles_c];
#pragma unroll
                for (int i = 0; i < TR; i++)
#pragma unroll
                    for (int j = 0; j < TC; j++)
                        acc[t][i][j] = fmaf(a[i], w[j], acc[t][i][j]);
            }
        }
    }

    // epilogue (dst regions are disjoint from src regions at every stage)
#pragma unroll
    for (int t = 0; t < TPT; t++) {
        const int tile = tid + t * THREADS;
        const int tc = tile % tiles_c;
        const int tr = tile / tiles_c;
#pragma unroll
        for (int j = 0; j < TC; j++) {
            const int c = tc + j * tiles_c;
#pragma unroll
            for (int i = 0; i < TR; i++) {
                const int r = tr * TR + i;
                float v = acc[t][i][j];
                if (EPI == 0) {
                    dst[c * PITCH + r] = frelu(v);
                } else if (EPI == 1) {
                    dst[c * PITCH + r] = frelu(v)
                        + redSrc[(2 * c) * PITCH + r]
                        + redSrc[(2 * c + 1) * PITCH + r];
                } else {
                    const int gr = row0 + r;
                    if (gr < Ntot) gout[(size_t)gr * COUT + c] = frelu(v);
                }
            }
        }
    }
}

// smem floats: sE1 32*65, sE2 64*65, sA 256*65, sB 128*65, sW 16384
#define SMEM_FLOATS ((32 + 64 + 256 + 128) * PITCH + 16384)
#define SMEM_BYTES  (SMEM_FLOATS * 4)

__global__ void __launch_bounds__(THREADS, 1)
fused_backbone_kernel(const float* __restrict__ feat,
                      const float* __restrict__ Win,
                      const float* __restrict__ We1, const float* __restrict__ We2,
                      const float* __restrict__ We3,
                      const float* __restrict__ Wl1, const float* __restrict__ Wl2,
                      const float* __restrict__ Wl3,
                      const float* __restrict__ Wm1, const float* __restrict__ Wm2,
                      const float* __restrict__ Wm3,
                      const float* __restrict__ Wu1, const float* __restrict__ Wu2,
                      const float* __restrict__ Wu3,
                      float* __restrict__ out, int Ntot)
{
    extern __shared__ float smem[];
    float* sE1 = smem;                       // e1: 32 ch
    float* sE2 = sE1 + 32 * PITCH;           // e2: 64 ch
    float* sA  = sE2 + 64 * PITCH;           // general / cat buffer: 256 ch
    float* sB  = sA + 256 * PITCH;           // general buffer: 128 ch
    float* sW  = sB + 128 * PITCH;           // weight stage buffer: 16384 f

    const int tid  = threadIdx.x;
    const int row0 = blockIdx.x * RROWS;

    // load feat[row0:row0+R, 0:16] transposed into sA (coalesced gmem reads)
    for (int idx = tid; idx < 16 * RROWS; idx += THREADS) {
        const int c = idx & 15, r = idx >> 4;
        const int gr = row0 + r;
        sA[c * PITCH + r] = (gr < Ntot) ? feat[(size_t)gr * 16 + c] : 0.f;
    }
    // (mm's leading __syncthreads covers this)

    // encoder
    mm<16, 32, 4, 2, 0>(sA, Win, sW, sB, nullptr, nullptr, 0, 0, tid);   // x   -> sB[0:32]
    mm<32, 32, 4, 2, 0>(sB, We1, sW, sE1, nullptr, nullptr, 0, 0, tid);  // e1  -> sE1
    mm<32, 64, 4, 4, 0>(sE1, We2, sW, sE2, nullptr, nullptr, 0, 0, tid); // e2  -> sE2
    mm<64, 128, 4, 4, 0>(sE2, We3, sW, sA, nullptr, nullptr, 0, 0, tid); // e3  -> sA[0:128]

    // decoder stage 3 (C=128): cat = [e3 | lat3] in sA[0:256]
    mm<128, 128, 4, 4, 0>(sA, Wl3, sW, sA + 128 * PITCH, nullptr, nullptr, 0, 0, tid); // lat3
    mm<256, 128, 4, 4, 1>(sA, Wm3, sW, sB, sA, nullptr, 0, 0, tid);      // t3 = relu(merge)+red -> sB[0:128]
    mm<128, 64, 4, 4, 0>(sB, Wu3, sW, sA, nullptr, nullptr, 0, 0, tid);  // x2 -> sA[0:64]

    // decoder stage 2 (C=64): cat = [x2 | lat2] in sA[0:128]
    mm<64, 64, 4, 4, 0>(sE2, Wl2, sW, sA + 64 * PITCH, nullptr, nullptr, 0, 0, tid);   // lat2
    mm<128, 64, 4, 4, 1>(sA, Wm2, sW, sB, sA, nullptr, 0, 0, tid);       // t2 -> sB[0:64]
    mm<64, 32, 4, 2, 0>(sB, Wu2, sW, sA, nullptr, nullptr, 0, 0, tid);   // x1 -> sA[0:32]

    // decoder stage 1 (C=32): cat = [x1 | lat1] in sA[0:64]
    mm<32, 32, 4, 2, 0>(sE1, Wl1, sW, sA + 32 * PITCH, nullptr, nullptr, 0, 0, tid);   // lat1
    mm<64, 32, 4, 2, 1>(sA, Wm1, sW, sB, sA, nullptr, 0, 0, tid);        // t1 -> sB[0:32]

    // final upsample -> global output [N, 32]
    mm<32, 32, 4, 2, 2>(sB, Wu1, sW, nullptr, nullptr, out, row0, Ntot, tid);
}

extern "C" void kernel_launch(void* const* d_in, const int* in_sizes, int n_in,
                              void* d_out, int out_size)
{
    const float* feat = (const float*)d_in[0];
    // d_in[1] = coords (int32) — defines sparse structure only; unused for 1x1 subm convs
    const float* Win = (const float*)d_in[2];
    const float* We1 = (const float*)d_in[3];
    const float* We2 = (const float*)d_in[4];
    const float* We3 = (const float*)d_in[5];
    const float* Wl1 = (const float*)d_in[6];
    const float* Wl2 = (const float*)d_in[7];
    const float* Wl3 = (const float*)d_in[8];
    const float* Wm1 = (const float*)d_in[9];
    const float* Wm2 = (const float*)d_in[10];
    const float* Wm3 = (const float*)d_in[11];
    const float* Wu1 = (const float*)d_in[12];
    const float* Wu2 = (const float*)d_in[13];
    const float* Wu3 = (const float*)d_in[14];

    const int N = in_sizes[0] / 16;

    cudaFuncSetAttribute(fused_backbone_kernel,
                         cudaFuncAttributeMaxDynamicSharedMemorySize, SMEM_BYTES);

    const int grid = (N + RROWS - 1) / RROWS;
    fused_backbone_kernel<<<grid, THREADS, SMEM_BYTES>>>(
        feat, Win, We1, We2, We3, Wl1, Wl2, Wl3,
        Wm1, Wm2, Wm3, Wu1, Wu2, Wu3, (float*)d_out, N);
}

// round 3
// speedup vs baseline: 1.1663x; 1.1663x over previous
#include <cuda_runtime.h>

// Fused sparse-UNet backbone, round 3: packed f32x2 FMA (2 MACs/lane/inst,
// same rt=2 issue rate as scalar FFMA -> 2x math throughput), wide broadcast
// LDS.128 for activations, per-thread-contiguous weight columns.
// R2 bug fixed: fma operand order was (acc, A, w) = acc*A + w; now (A, w, acc).
//
// Layout: activations channel-major in SMEM, PITCH=68 floats (16B-alignable).
// Tiling: every stage uses tiles_c=32 (tc = lane id) so all lanes of a warp
// share tr -> activation loads are pure broadcasts. TR=8 rows/thread as 4
// f32x2 pairs, TC=COUT/32 columns/thread.

#define THREADS 256
#define RROWS   64
#define PITCH   68

typedef unsigned long long ull;

__device__ __forceinline__ ull fma2(ull a, ull b, ull c) {
    ull d;
    asm("fma.rn.f32x2 %0, %1, %2, %3;" : "=l"(d) : "l"(a), "l"(b), "l"(c));
    return d;
}
__device__ __forceinline__ ull dup2(float x) {
    ull r;
    asm("mov.b64 %0, {%1, %1};" : "=l"(r) : "f"(x));
    return r;
}
__device__ __forceinline__ float2 unpk2(ull v) {
    float2 r;
    asm("mov.b64 {%0, %1}, %2;" : "=f"(r.x), "=f"(r.y) : "l"(v));
    return r;
}
__device__ __forceinline__ float frelu(float v) { return v > 0.f ? v : 0.f; }

// EPI: 0 relu->smem ; 1 relu(acc)+pairsum(redSrc)->smem ; 2 relu->gmem [N,COUT]
template<int CIN, int COUT, int EPI>
__device__ __forceinline__ void mm2(const float* __restrict__ sSrc,
                                    const float* __restrict__ Wg,
                                    float* __restrict__ sW,
                                    float* __restrict__ dst,
                                    const float* __restrict__ redSrc,
                                    float* __restrict__ gout,
                                    int row0, int Ntot, int tid)
{
    constexpr int TC     = COUT / 32;                 // cols per thread (1,2,4)
    constexpr int NCHUNK = (CIN > 128) ? (CIN / 128) : 1;
    constexpr int KC     = CIN / NCHUNK;              // <= 128

    const int tc = tid & 31;                          // lane
    const int tr = tid >> 5;                          // warp id: rows tr*8..tr*8+7

    ull acc[4][TC];
#pragma unroll
    for (int p = 0; p < 4; p++)
#pragma unroll
        for (int j = 0; j < TC; j++) acc[p][j] = 0ull;

    for (int ch = 0; ch < NCHUNK; ch++) {
        __syncthreads();                              // prev stage done / sW free
        {
            const float4* ws = (const float4*)(Wg + (size_t)ch * KC * COUT);
            float4* wd = (float4*)sW;
            constexpr int WN = KC * COUT / 4;
            for (int i = tid; i < WN; i += THREADS) wd[i] = ws[i];
        }
        __syncthreads();

        const float* sp = sSrc + (size_t)ch * KC * PITCH + tr * 8;
#pragma unroll 4
        for (int k = 0; k < KC; k++) {
            const ulonglong2* ap = (const ulonglong2*)(sp + k * PITCH);
            ulonglong2 a01 = ap[0];                   // rows 0-3 (broadcast LDS.128)
            ulonglong2 a23 = ap[1];                   // rows 4-7
            ull A[4] = { a01.x, a01.y, a23.x, a23.y };

            const float* wp = sW + k * COUT + tc * TC;
            float w[TC];
            if constexpr (TC == 4) {
                float4 t = *(const float4*)wp;
                w[0] = t.x; w[1] = t.y; w[2] = t.z; w[3] = t.w;
            } else if constexpr (TC == 2) {
                float2 t = *(const float2*)wp;
                w[0] = t.x; w[1] = t.y;
            } else {
                w[0] = *wp;
            }
#pragma unroll
            for (int j = 0; j < TC; j++) {
                ull wj = dup2(w[j]);
#pragma unroll
                for (int p = 0; p < 4; p++)
                    acc[p][j] = fma2(A[p], wj, acc[p][j]);   // d = A*w + acc
            }
        }
    }

    // epilogue (dst regions disjoint from src regions at every stage)
#pragma unroll
    for (int j = 0; j < TC; j++) {
        const int c = tc * TC + j;
#pragma unroll
        for (int p = 0; p < 4; p++) {
            float2 v = unpk2(acc[p][j]);
            const int r0 = tr * 8 + 2 * p;
            if (EPI == 0) {
                dst[c * PITCH + r0]     = frelu(v.x);
                dst[c * PITCH + r0 + 1] = frelu(v.y);
            } else if (EPI == 1) {
                dst[c * PITCH + r0]     = frelu(v.x)
                    + redSrc[(2 * c) * PITCH + r0] + redSrc[(2 * c + 1) * PITCH + r0];
                dst[c * PITCH + r0 + 1] = frelu(v.y)
                    + redSrc[(2 * c) * PITCH + r0 + 1] + redSrc[(2 * c + 1) * PITCH + r0 + 1];
            } else {
                const int g0 = row0 + r0;
                if (g0 < Ntot)     gout[(size_t)g0 * COUT + c] = frelu(v.x);
                if (g0 + 1 < Ntot) gout[(size_t)(g0 + 1) * COUT + c] = frelu(v.y);
            }
        }
    }
}

// smem floats: sE1 32*P, sE2 64*P, sA 256*P, sB 128*P, sW 16384
#define SMEM_FLOATS ((32 + 64 + 256 + 128) * PITCH + 16384)
#define SMEM_BYTES  (SMEM_FLOATS * 4)

__global__ void __launch_bounds__(THREADS, 1)
fused_backbone_kernel(const float* __restrict__ feat,
                      const float* __restrict__ Win,
                      const float* __restrict__ We1, const float* __restrict__ We2,
                      const float* __restrict__ We3,
                      const float* __restrict__ Wl1, const float* __restrict__ Wl2,
                      const float* __restrict__ Wl3,
                      const float* __restrict__ Wm1, const float* __restrict__ Wm2,
                      const float* __restrict__ Wm3,
                      const float* __restrict__ Wu1, const float* __restrict__ Wu2,
                      const float* __restrict__ Wu3,
                      float* __restrict__ out, int Ntot)
{
    extern __shared__ float smem[];
    float* sE1 = smem;                       // e1: 32 ch
    float* sE2 = sE1 + 32 * PITCH;           // e2: 64 ch
    float* sA  = sE2 + 64 * PITCH;           // general / cat buffer: 256 ch
    float* sB  = sA + 256 * PITCH;           // general buffer: 128 ch
    float* sW  = sB + 128 * PITCH;           // weight stage buffer: 16384 f

    const int tid  = threadIdx.x;
    const int row0 = blockIdx.x * RROWS;

    // load feat[row0:row0+R, 0:16] transposed into sA (coalesced gmem reads)
    for (int idx = tid; idx < 16 * RROWS; idx += THREADS) {
        const int c = idx & 15, r = idx >> 4;
        const int gr = row0 + r;
        sA[c * PITCH + r] = (gr < Ntot) ? feat[(size_t)gr * 16 + c] : 0.f;
    }
    // (mm2's leading __syncthreads covers this)

    // encoder
    mm2<16, 32, 0>(sA, Win, sW, sB, nullptr, nullptr, 0, 0, tid);    // x   -> sB[0:32]
    mm2<32, 32, 0>(sB, We1, sW, sE1, nullptr, nullptr, 0, 0, tid);   // e1  -> sE1
    mm2<32, 64, 0>(sE1, We2, sW, sE2, nullptr, nullptr, 0, 0, tid);  // e2  -> sE2
    mm2<64, 128, 0>(sE2, We3, sW, sA, nullptr, nullptr, 0, 0, tid);  // e3  -> sA[0:128]

    // decoder stage 3 (C=128): cat = [e3 | lat3] in sA[0:256]
    mm2<128, 128, 0>(sA, Wl3, sW, sA + 128 * PITCH, nullptr, nullptr, 0, 0, tid); // lat3
    mm2<256, 128, 1>(sA, Wm3, sW, sB, sA, nullptr, 0, 0, tid);       // t3 -> sB[0:128]
    mm2<128, 64, 0>(sB, Wu3, sW, sA, nullptr, nullptr, 0, 0, tid);   // x2 -> sA[0:64]

    // decoder stage 2 (C=64): cat = [x2 | lat2] in sA[0:128]
    mm2<64, 64, 0>(sE2, Wl2, sW, sA + 64 * PITCH, nullptr, nullptr, 0, 0, tid);   // lat2
    mm2<128, 64, 1>(sA, Wm2, sW, sB, sA, nullptr, 0, 0, tid);        // t2 -> sB[0:64]
    mm2<64, 32, 0>(sB, Wu2, sW, sA, nullptr, nullptr, 0, 0, tid);    // x1 -> sA[0:32]

    // decoder stage 1 (C=32): cat = [x1 | lat1] in sA[0:64]
    mm2<32, 32, 0>(sE1, Wl1, sW, sA + 32 * PITCH, nullptr, nullptr, 0, 0, tid);   // lat1
    mm2<64, 32, 1>(sA, Wm1, sW, sB, sA, nullptr, 0, 0, tid);         // t1 -> sB[0:32]

    // final upsample -> global output [N, 32]
    mm2<32, 32, 2>(sB, Wu1, sW, nullptr, nullptr, out, row0, Ntot, tid);
}

extern "C" void kernel_launch(void* const* d_in, const int* in_sizes, int n_in,
                              void* d_out, int out_size)
{
    const float* feat = (const float*)d_in[0];
    // d_in[1] = coords (int32) — sparse structure only; unused for 1x1 subm convs
    const float* Win = (const float*)d_in[2];
    const float* We1 = (const float*)d_in[3];
    const float* We2 = (const float*)d_in[4];
    const float* We3 = (const float*)d_in[5];
    const float* Wl1 = (const float*)d_in[6];
    const float* Wl2 = (const float*)d_in[7];
    const float* Wl3 = (const float*)d_in[8];
    const float* Wm1 = (const float*)d_in[9];
    const float* Wm2 = (const float*)d_in[10];
    const float* Wm3 = (const float*)d_in[11];
    const float* Wu1 = (const float*)d_in[12];
    const float* Wu2 = (const float*)d_in[13];
    const float* Wu3 = (const float*)d_in[14];

    const int N = in_sizes[0] / 16;

    cudaFuncSetAttribute(fused_backbone_kernel,
                         cudaFuncAttributeMaxDynamicSharedMemorySize, SMEM_BYTES);

    const int grid = (N + RROWS - 1) / RROWS;
    fused_backbone_kernel<<<grid, THREADS, SMEM_BYTES>>>(
        feat, Win, We1, We2, We3, Wl1, Wl2, Wl3,
        Wm1, Wm2, Wm3, Wu1, Wu2, Wu3, (float*)d_out, N);
}

// round 4
// speedup vs baseline: 1.1688x; 1.0021x over previous
#include <cuda_runtime.h>

// Fused sparse-UNet backbone, round 3: packed f32x2 FMA (2 MACs/lane/inst,
// same rt=2 issue rate as scalar FFMA -> 2x math throughput), wide broadcast
// LDS.128 for activations, per-thread-contiguous weight columns.
// R2 bug fixed: fma operand order was (acc, A, w) = acc*A + w; now (A, w, acc).
//
// Layout: activations channel-major in SMEM, PITCH=68 floats (16B-alignable).
// Tiling: every stage uses tiles_c=32 (tc = lane id) so all lanes of a warp
// share tr -> activation loads are pure broadcasts. TR=8 rows/thread as 4
// f32x2 pairs, TC=COUT/32 columns/thread.

#define THREADS 256
#define RROWS   64
#define PITCH   68

typedef unsigned long long ull;

__device__ __forceinline__ ull fma2(ull a, ull b, ull c) {
    ull d;
    asm("fma.rn.f32x2 %0, %1, %2, %3;" : "=l"(d) : "l"(a), "l"(b), "l"(c));
    return d;
}
__device__ __forceinline__ ull dup2(float x) {
    ull r;
    asm("mov.b64 %0, {%1, %1};" : "=l"(r) : "f"(x));
    return r;
}
__device__ __forceinline__ float2 unpk2(ull v) {
    float2 r;
    asm("mov.b64 {%0, %1}, %2;" : "=f"(r.x), "=f"(r.y) : "l"(v));
    return r;
}
__device__ __forceinline__ float frelu(float v) { return v > 0.f ? v : 0.f; }

// EPI: 0 relu->smem ; 1 relu(acc)+pairsum(redSrc)->smem ; 2 relu->gmem [N,COUT]
template<int CIN, int COUT, int EPI>
__device__ __forceinline__ void mm2(const float* __restrict__ sSrc,
                                    const float* __restrict__ Wg,
                                    float* __restrict__ sW,
                                    float* __restrict__ dst,
                                    const float* __restrict__ redSrc,
                                    float* __restrict__ gout,
                                    int row0, int Ntot, int tid)
{
    constexpr int TC     = COUT / 32;                 // cols per thread (1,2,4)
    constexpr int NCHUNK = (CIN > 128) ? (CIN / 128) : 1;
    constexpr int KC     = CIN / NCHUNK;              // <= 128

    const int tc = tid & 31;                          // lane
    const int tr = tid >> 5;                          // warp id: rows tr*8..tr*8+7

    ull acc[4][TC];
#pragma unroll
    for (int p = 0; p < 4; p++)
#pragma unroll
        for (int j = 0; j < TC; j++) acc[p][j] = 0ull;

    for (int ch = 0; ch < NCHUNK; ch++) {
        __syncthreads();                              // prev stage done / sW free
        {
            const float4* ws = (const float4*)(Wg + (size_t)ch * KC * COUT);
            float4* wd = (float4*)sW;
            constexpr int WN = KC * COUT / 4;
            for (int i = tid; i < WN; i += THREADS) wd[i] = ws[i];
        }
        __syncthreads();

        const float* sp = sSrc + (size_t)ch * KC * PITCH + tr * 8;
#pragma unroll 4
        for (int k = 0; k < KC; k++) {
            const ulonglong2* ap = (const ulonglong2*)(sp + k * PITCH);
            ulonglong2 a01 = ap[0];                   // rows 0-3 (broadcast LDS.128)
            ulonglong2 a23 = ap[1];                   // rows 4-7
            ull A[4] = { a01.x, a01.y, a23.x, a23.y };

            const float* wp = sW + k * COUT + tc * TC;
            float w[TC];
            if constexpr (TC == 4) {
                float4 t = *(const float4*)wp;
                w[0] = t.x; w[1] = t.y; w[2] = t.z; w[3] = t.w;
            } else if constexpr (TC == 2) {
                float2 t = *(const float2*)wp;
                w[0] = t.x; w[1] = t.y;
            } else {
                w[0] = *wp;
            }
#pragma unroll
            for (int j = 0; j < TC; j++) {
                ull wj = dup2(w[j]);
#pragma unroll
                for (int p = 0; p < 4; p++)
                    acc[p][j] = fma2(A[p], wj, acc[p][j]);   // d = A*w + acc
            }
        }
    }

    // epilogue (dst regions disjoint from src regions at every stage)
#pragma unroll
    for (int j = 0; j < TC; j++) {
        const int c = tc * TC + j;
#pragma unroll
        for (int p = 0; p < 4; p++) {
            float2 v = unpk2(acc[p][j]);
            const int r0 = tr * 8 + 2 * p;
            if (EPI == 0) {
                dst[c * PITCH + r0]     = frelu(v.x);
                dst[c * PITCH + r0 + 1] = frelu(v.y);
            } else if (EPI == 1) {
                dst[c * PITCH + r0]     = frelu(v.x)
                    + redSrc[(2 * c) * PITCH + r0] + redSrc[(2 * c + 1) * PITCH + r0];
                dst[c * PITCH + r0 + 1] = frelu(v.y)
                    + redSrc[(2 * c) * PITCH + r0 + 1] + redSrc[(2 * c + 1) * PITCH + r0 + 1];
            } else {
                const int g0 = row0 + r0;
                if (g0 < Ntot)     gout[(size_t)g0 * COUT + c] = frelu(v.x);
                if (g0 + 1 < Ntot) gout[(size_t)(g0 + 1) * COUT + c] = frelu(v.y);
            }
        }
    }
}

// smem floats: sE1 32*P, sE2 64*P, sA 256*P, sB 128*P, sW 16384
#define SMEM_FLOATS ((32 + 64 + 256 + 128) * PITCH + 16384)
#define SMEM_BYTES  (SMEM_FLOATS * 4)

__global__ void __launch_bounds__(THREADS, 1)
fused_backbone_kernel(const float* __restrict__ feat,
                      const float* __restrict__ Win,
                      const float* __restrict__ We1, const float* __restrict__ We2,
                      const float* __restrict__ We3,
                      const float* __restrict__ Wl1, const float* __restrict__ Wl2,
                      const float* __restrict__ Wl3,
                      const float* __restrict__ Wm1, const float* __restrict__ Wm2,
                      const float* __restrict__ Wm3,
                      const float* __restrict__ Wu1, const float* __restrict__ Wu2,
                      const float* __restrict__ Wu3,
                      float* __restrict__ out, int Ntot)
{
    extern __shared__ float smem[];
    float* sE1 = smem;                       // e1: 32 ch
    float* sE2 = sE1 + 32 * PITCH;           // e2: 64 ch
    float* sA  = sE2 + 64 * PITCH;           // general / cat buffer: 256 ch
    float* sB  = sA + 256 * PITCH;           // general buffer: 128 ch
    float* sW  = sB + 128 * PITCH;           // weight stage buffer: 16384 f

    const int tid  = threadIdx.x;
    const int row0 = blockIdx.x * RROWS;

    // load feat[row0:row0+R, 0:16] transposed into sA (coalesced gmem reads)
    for (int idx = tid; idx < 16 * RROWS; idx += THREADS) {
        const int c = idx & 15, r = idx >> 4;
        const int gr = row0 + r;
        sA[c * PITCH + r] = (gr < Ntot) ? feat[(size_t)gr * 16 + c] : 0.f;
    }
    // (mm2's leading __syncthreads covers this)

    // encoder
    mm2<16, 32, 0>(sA, Win, sW, sB, nullptr, nullptr, 0, 0, tid);    // x   -> sB[0:32]
    mm2<32, 32, 0>(sB, We1, sW, sE1, nullptr, nullptr, 0, 0, tid);   // e1  -> sE1
    mm2<32, 64, 0>(sE1, We2, sW, sE2, nullptr, nullptr, 0, 0, tid);  // e2  -> sE2
    mm2<64, 128, 0>(sE2, We3, sW, sA, nullptr, nullptr, 0, 0, tid);  // e3  -> sA[0:128]

    // decoder stage 3 (C=128): cat = [e3 | lat3] in sA[0:256]
    mm2<128, 128, 0>(sA, Wl3, sW, sA + 128 * PITCH, nullptr, nullptr, 0, 0, tid); // lat3
    mm2<256, 128, 1>(sA, Wm3, sW, sB, sA, nullptr, 0, 0, tid);       // t3 -> sB[0:128]
    mm2<128, 64, 0>(sB, Wu3, sW, sA, nullptr, nullptr, 0, 0, tid);   // x2 -> sA[0:64]

    // decoder stage 2 (C=64): cat = [x2 | lat2] in sA[0:128]
    mm2<64, 64, 0>(sE2, Wl2, sW, sA + 64 * PITCH, nullptr, nullptr, 0, 0, tid);   // lat2
    mm2<128, 64, 1>(sA, Wm2, sW, sB, sA, nullptr, 0, 0, tid);        // t2 -> sB[0:64]
    mm2<64, 32, 0>(sB, Wu2, sW, sA, nullptr, nullptr, 0, 0, tid);    // x1 -> sA[0:32]

    // decoder stage 1 (C=32): cat = [x1 | lat1] in sA[0:64]
    mm2<32, 32, 0>(sE1, Wl1, sW, sA + 32 * PITCH, nullptr, nullptr, 0, 0, tid);   // lat1
    mm2<64, 32, 1>(sA, Wm1, sW, sB, sA, nullptr, 0, 0, tid);         // t1 -> sB[0:32]

    // final upsample -> global output [N, 32]
    mm2<32, 32, 2>(sB, Wu1, sW, nullptr, nullptr, out, row0, Ntot, tid);
}

extern "C" void kernel_launch(void* const* d_in, const int* in_sizes, int n_in,
                              void* d_out, int out_size)
{
    const float* feat = (const float*)d_in[0];
    // d_in[1] = coords (int32) — sparse structure only; unused for 1x1 subm convs
    const float* Win = (const float*)d_in[2];
    const float* We1 = (const float*)d_in[3];
    const float* We2 = (const float*)d_in[4];
    const float* We3 = (const float*)d_in[5];
    const float* Wl1 = (const float*)d_in[6];
    const float* Wl2 = (const float*)d_in[7];
    const float* Wl3 = (const float*)d_in[8];
    const float* Wm1 = (const float*)d_in[9];
    const float* Wm2 = (const float*)d_in[10];
    const float* Wm3 = (const float*)d_in[11];
    const float* Wu1 = (const float*)d_in[12];
    const float* Wu2 = (const float*)d_in[13];
    const float* Wu3 = (const float*)d_in[14];

    const int N = in_sizes[0] / 16;

    cudaFuncSetAttribute(fused_backbone_kernel,
                         cudaFuncAttributeMaxDynamicSharedMemorySize, SMEM_BYTES);

    const int grid = (N + RROWS - 1) / RROWS;
    fused_backbone_kernel<<<grid, THREADS, SMEM_BYTES>>>(
        feat, Win, We1, We2, We3, Wl1, Wl2, Wl3,
        Wm1, Wm2, Wm3, Wu1, Wu2, Wu3, (float*)d_out, N);
}

// round 5
// speedup vs baseline: 1.4209x; 1.2157x over previous
#include <cuda_runtime.h>

// Fused sparse-UNet backbone, round 5.
// Key change vs R4: 128 rows/CTA, 16 rows per warp (8 f32x2 accumulators per
// output column) -> 32 FFMA2 per warp-k vs 12 crossbar wavefronts: FFMA2-bound.
// Epilogues are register-deferred (compute -> regs -> sync -> store) so stage
// src/dst buffers may alias; removes the 128-ch spill buffer and fits 1 CTA/SM.

#define THREADS 256
#define RROWS   128
#define PITCH   132          // floats; 132*4=528 B, 16B-aligned rows
#define WBUF    8192         // weight staging buffer, floats (32 KB)

typedef unsigned long long ull;

__device__ __forceinline__ ull fma2(ull a, ull b, ull c) {
    ull d;
    asm("fma.rn.f32x2 %0, %1, %2, %3;" : "=l"(d) : "l"(a), "l"(b), "l"(c));
    return d;
}
__device__ __forceinline__ ull dup2(float x) {
    ull r;
    asm("mov.b64 %0, {%1, %1};" : "=l"(r) : "f"(x));
    return r;
}
__device__ __forceinline__ float2 unpk2(ull v) {
    float2 r;
    asm("mov.b64 {%0, %1}, %2;" : "=f"(r.x), "=f"(r.y) : "l"(v));
    return r;
}
__device__ __forceinline__ ull pk2(float2 v) {
    ull r;
    asm("mov.b64 %0, {%1, %2};" : "=l"(r) : "f"(v.x), "f"(v.y));
    return r;
}
__device__ __forceinline__ float frelu(float v) { return v > 0.f ? v : 0.f; }

// EPI: 0 relu->smem ; 1 relu+pairsum(redSrc)->smem ; 2 relu->gmem [N,COUT]
// Warp w owns rows [16w, 16w+16). Lane owns COUT/32 contiguous columns.
template<int CIN, int COUT, int EPI>
__device__ __forceinline__ void mm2(const float* __restrict__ sSrc,
                                    const float* __restrict__ Wg,
                                    float* __restrict__ sW,
                                    float* __restrict__ dst,
                                    const float* __restrict__ redSrc,
                                    float* __restrict__ gout,
                                    int row0, int Ntot, int tid)
{
    constexpr int TC  = COUT / 32;                         // 1, 2 or 4
    constexpr int KCC = (WBUF / COUT < CIN) ? (WBUF / COUT) : CIN;
    constexpr int NCH = CIN / KCC;                          // exact (pow2 sizes)

    const int lane = tid & 31;
    const int warp = tid >> 5;
    const int rbase = warp * 16;

    ull acc[8][TC];
#pragma unroll
    for (int p = 0; p < 8; p++)
#pragma unroll
        for (int j = 0; j < TC; j++) acc[p][j] = 0ull;

    for (int ch = 0; ch < NCH; ch++) {
        __syncthreads();                                    // sW free / prev stores visible
        {
            const float4* ws = (const float4*)(Wg + (size_t)ch * KCC * COUT);
            float4* wd = (float4*)sW;
            constexpr int WN = KCC * COUT / 4;
            for (int i = tid; i < WN; i += THREADS) wd[i] = ws[i];
        }
        __syncthreads();

        const float* sp = sSrc + (size_t)ch * KCC * PITCH + rbase;
#pragma unroll 4
        for (int k = 0; k < KCC; k++) {
            const ulonglong2* ap = (const ulonglong2*)(sp + k * PITCH);
            ulonglong2 a01 = ap[0];                         // rows 0-3  (broadcast)
            ulonglong2 a23 = ap[1];                         // rows 4-7
            ulonglong2 a45 = ap[2];                         // rows 8-11
            ulonglong2 a67 = ap[3];                         // rows 12-15
            ull A[8] = { a01.x, a01.y, a23.x, a23.y, a45.x, a45.y, a67.x, a67.y };

            const float* wp = sW + k * COUT + lane * TC;
            float w[TC];
            if constexpr (TC == 4) {
                float4 t = *(const float4*)wp;
                w[0] = t.x; w[1] = t.y; w[2] = t.z; w[3] = t.w;
            } else if constexpr (TC == 2) {
                float2 t = *(const float2*)wp;
                w[0] = t.x; w[1] = t.y;
            } else {
                w[0] = *wp;
            }
#pragma unroll
            for (int j = 0; j < TC; j++) {
                ull wj = dup2(w[j]);
#pragma unroll
                for (int p = 0; p < 8; p++)
                    acc[p][j] = fma2(A[p], wj, acc[p][j]);  // A*w + acc
            }
        }
    }

    // finalize into registers (reads of redSrc happen BEFORE the sync)
#pragma unroll
    for (int j = 0; j < TC; j++) {
        const int c = lane * TC + j;
#pragma unroll
        for (int p = 0; p < 8; p++) {
            float2 v = unpk2(acc[p][j]);
            v.x = frelu(v.x); v.y = frelu(v.y);
            if (EPI == 1) {
                const int r0 = rbase + 2 * p;
                const float2 ra = *(const float2*)&redSrc[(2 * c) * PITCH + r0];
                const float2 rb = *(const float2*)&redSrc[(2 * c + 1) * PITCH + r0];
                v.x += ra.x + rb.x;
                v.y += ra.y + rb.y;
            }
            acc[p][j] = pk2(v);
        }
    }

    if (EPI == 2) {
        // final stage: straight to gmem, no smem hazard
#pragma unroll
        for (int j = 0; j < TC; j++) {
            const int c = lane * TC + j;
#pragma unroll
            for (int p = 0; p < 8; p++) {
                float2 v = unpk2(acc[p][j]);
                const int g0 = row0 + rbase + 2 * p;
                if (g0 < Ntot)     gout[(size_t)g0 * COUT + c]       = v.x;
                if (g0 + 1 < Ntot) gout[(size_t)(g0 + 1) * COUT + c] = v.y;
            }
        }
        return;
    }

    __syncthreads();                                        // all reads of src done
#pragma unroll
    for (int j = 0; j < TC; j++) {
        const int c = lane * TC + j;
#pragma unroll
        for (int p = 0; p < 8; p++) {
            const int r0 = rbase + 2 * p;
            *(float2*)&dst[c * PITCH + r0] = unpk2(acc[p][j]);
        }
    }
}

// smem: sE1 32ch, sE2 64ch, sC 256ch (all PITCH floats/ch) + sW
#define SMEM_FLOATS ((32 + 64 + 256) * PITCH + WBUF)
#define SMEM_BYTES  (SMEM_FLOATS * 4)

__global__ void __launch_bounds__(THREADS, 1)
fused_backbone_kernel(const float* __restrict__ feat,
                      const float* __restrict__ Win,
                      const float* __restrict__ We1, const float* __restrict__ We2,
                      const float* __restrict__ We3,
                      const float* __restrict__ Wl1, const float* __restrict__ Wl2,
                      const float* __restrict__ Wl3,
                      const float* __restrict__ Wm1, const float* __restrict__ Wm2,
                      const float* __restrict__ Wm3,
                      const float* __restrict__ Wu1, const float* __restrict__ Wu2,
                      const float* __restrict__ Wu3,
                      float* __restrict__ out, int Ntot)
{
    extern __shared__ float smem[];
    float* sE1 = smem;                        // e1: 32 ch (persists)
    float* sE2 = sE1 + 32 * PITCH;            // e2: 64 ch (persists)
    float* sC  = sE2 + 64 * PITCH;            // workspace: 256 ch
    float* sW  = sC + 256 * PITCH;            // weight chunk buffer

    const int tid  = threadIdx.x;
    const int row0 = blockIdx.x * RROWS;

    // feat[row0 : row0+128, 0:16] -> sC[0:16] channel-major (coalesced reads)
    for (int idx = tid; idx < 16 * RROWS; idx += THREADS) {
        const int c = idx & 15, r = idx >> 4;
        const int gr = row0 + r;
        sC[c * PITCH + r] = (gr < Ntot) ? feat[(size_t)gr * 16 + c] : 0.f;
    }
    // mm2's leading __syncthreads covers the store->read hazard

    // encoder (src/dst may alias: epilogues are reg-deferred)
    mm2<16, 32, 0>(sC, Win, sW, sC, nullptr, nullptr, 0, 0, tid);    // x   -> sC[0:32]
    mm2<32, 32, 0>(sC, We1, sW, sE1, nullptr, nullptr, 0, 0, tid);   // e1  -> sE1
    mm2<32, 64, 0>(sE1, We2, sW, sE2, nullptr, nullptr, 0, 0, tid);  // e2  -> sE2
    mm2<64, 128, 0>(sE2, We3, sW, sC, nullptr, nullptr, 0, 0, tid);  // e3  -> sC[0:128]

    // decoder stage 3 (C=128): cat3 = [e3 | lat3] = sC[0:256]
    mm2<128, 128, 0>(sC, Wl3, sW, sC + 128 * PITCH, nullptr, nullptr, 0, 0, tid); // lat3
    mm2<256, 128, 1>(sC, Wm3, sW, sC, sC, nullptr, 0, 0, tid);       // t3 -> sC[0:128]
    mm2<128, 64, 0>(sC, Wu3, sW, sC, nullptr, nullptr, 0, 0, tid);   // x2 -> sC[0:64]

    // decoder stage 2 (C=64): cat2 = [x2 | lat2] = sC[0:128]
    mm2<64, 64, 0>(sE2, Wl2, sW, sC + 64 * PITCH, nullptr, nullptr, 0, 0, tid);   // lat2
    mm2<128, 64, 1>(sC, Wm2, sW, sC, sC, nullptr, 0, 0, tid);        // t2 -> sC[0:64]
    mm2<64, 32, 0>(sC, Wu2, sW, sC, nullptr, nullptr, 0, 0, tid);    // x1 -> sC[0:32]

    // decoder stage 1 (C=32): cat1 = [x1 | lat1] = sC[0:64]
    mm2<32, 32, 0>(sE1, Wl1, sW, sC + 32 * PITCH, nullptr, nullptr, 0, 0, tid);   // lat1
    mm2<64, 32, 1>(sC, Wm1, sW, sC, sC, nullptr, 0, 0, tid);         // t1 -> sC[0:32]

    // final upsample -> gmem [N, 32]
    mm2<32, 32, 2>(sC, Wu1, sW, nullptr, nullptr, out, row0, Ntot, tid);
}

extern "C" void kernel_launch(void* const* d_in, const int* in_sizes, int n_in,
                              void* d_out, int out_size)
{
    const float* feat = (const float*)d_in[0];
    // d_in[1] = coords (int32) — sparse structure only; unused for 1x1 subm convs
    const float* Win = (const float*)d_in[2];
    const float* We1 = (const float*)d_in[3];
    const float* We2 = (const float*)d_in[4];
    const float* We3 = (const float*)d_in[5];
    const float* Wl1 = (const float*)d_in[6];
    const float* Wl2 = (const float*)d_in[7];
    const float* Wl3 = (const float*)d_in[8];
    const float* Wm1 = (const float*)d_in[9];
    const float* Wm2 = (const float*)d_in[10];
    const float* Wm3 = (const float*)d_in[11];
    const float* Wu1 = (const float*)d_in[12];
    const float* Wu2 = (const float*)d_in[13];
    const float* Wu3 = (const float*)d_in[14];

    const int N = in_sizes[0] / 16;

    cudaFuncSetAttribute(fused_backbone_kernel,
                         cudaFuncAttributeMaxDynamicSharedMemorySize, SMEM_BYTES);

    const int grid = (N + RROWS - 1) / RROWS;
    fused_backbone_kernel<<<grid, THREADS, SMEM_BYTES>>>(
        feat, Win, We1, We2, We3, Wl1, Wl2, Wl3,
        Wm1, Wm2, Wm3, Wu1, Wu2, Wu3, (float*)d_out, N);
}